// round 5
// baseline (speedup 1.0000x reference)
#include <cuda_runtime.h>
#include <cstdint>

// Problem shape (fixed by the dataset)
#define Nn 8
#define Cc 32
#define Hh 512
#define Ww 512
#define HW (Hh * Ww)          // 262144
#define OC 32
#define NPIX ((long)Nn * HW)  // 2,097,152 pixels

// ---------------- device scratch (allocation-free rule: __device__ globals) ---
__device__ unsigned g_amax_x_bits;          // bit pattern of max|x| (nonneg float)
__device__ float    g_scale;                // sx*sw/127^2
__device__ float    g_invsx;                // 127/sx
__device__ int8_t   g_qw[OC * 9 * Cc];      // [oc][tap][ic], tap = kh*3+kw
__device__ int8_t   g_qx[(size_t)Nn * HW * Cc]; // NHWC int8, 64 MB

// ---------------- kernel 0: reset reduction state (graph replays need this) ---
__global__ void k_init() {
    g_amax_x_bits = 0u;
}

// ---------------- kernel 1: max|x| over 67M floats --------------------------
__global__ void k_absmax_x(const float4* __restrict__ x, int n4) {
    float m = 0.f;
    for (int i = blockIdx.x * blockDim.x + threadIdx.x; i < n4;
         i += gridDim.x * blockDim.x) {
        float4 v = x[i];
        m = fmaxf(m, fmaxf(fmaxf(fabsf(v.x), fabsf(v.y)),
                           fmaxf(fabsf(v.z), fabsf(v.w))));
    }
    #pragma unroll
    for (int o = 16; o; o >>= 1) m = fmaxf(m, __shfl_xor_sync(~0u, m, o));
    __shared__ float sm[32];
    int wid = threadIdx.x >> 5;
    if ((threadIdx.x & 31) == 0) sm[wid] = m;
    __syncthreads();
    if (threadIdx.x < 32) {
        float v = (threadIdx.x < (blockDim.x >> 5)) ? sm[threadIdx.x] : 0.f;
        #pragma unroll
        for (int o = 16; o; o >>= 1) v = fmaxf(v, __shfl_xor_sync(~0u, v, o));
        if (threadIdx.x == 0)
            atomicMax(&g_amax_x_bits, __float_as_uint(v)); // nonneg: uint order == float order
    }
}

// ---------------- kernel 2: weight amax + quantize + scales ------------------
// One block of 256 threads. Runs after k_absmax_x (same stream).
__global__ void k_prep_w(const float* __restrict__ w) {
    const int NW = OC * Cc * 9; // 9216
    float m = 0.f;
    for (int i = threadIdx.x; i < NW; i += 256) m = fmaxf(m, fabsf(w[i]));
    #pragma unroll
    for (int o = 16; o; o >>= 1) m = fmaxf(m, __shfl_xor_sync(~0u, m, o));
    __shared__ float sm[8];
    __shared__ float s_sw;
    if ((threadIdx.x & 31) == 0) sm[threadIdx.x >> 5] = m;
    __syncthreads();
    if (threadIdx.x == 0) {
        float v = sm[0];
        #pragma unroll
        for (int j = 1; j < 8; j++) v = fmaxf(v, sm[j]);
        s_sw = v;
    }
    __syncthreads();
    float inv = 127.f / s_sw;
    for (int i = threadIdx.x; i < NW; i += 256) {
        int oc = i / (Cc * 9);
        int r  = i % (Cc * 9);
        int ic = r / 9;
        int t  = r % 9;
        int q = __float2int_rn(w[i] * inv);   // round-half-to-even == jnp.round
        q = max(-127, min(127, q));
        g_qw[(oc * 9 + t) * Cc + ic] = (int8_t)q;
    }
    if (threadIdx.x == 0) {
        float sx = __uint_as_float(g_amax_x_bits);
        g_scale  = sx * s_sw / (127.f * 127.f);
        g_invsx  = 127.f / sx;
    }
}

// ---------------- kernel 3: quantize x, NCHW fp32 -> NHWC int8 ---------------
// One thread per pixel (n,h,w): 32 strided-coalesced reads, one 32B write.
__global__ void k_quant_x(const float* __restrict__ x) {
    long pix = (long)blockIdx.x * blockDim.x + threadIdx.x;
    if (pix >= NPIX) return;
    int n  = (int)(pix / HW);
    int hw = (int)(pix % HW);
    const float* xp = x + (size_t)n * Cc * HW + hw;
    float inv = g_invsx;
    uint32_t packed[8];
    #pragma unroll
    for (int cq = 0; cq < 8; cq++) {
        uint32_t p = 0;
        #pragma unroll
        for (int j = 0; j < 4; j++) {
            float v = __ldg(xp + (size_t)(cq * 4 + j) * HW);
            int q = __float2int_rn(v * inv);
            q = max(-127, min(127, q));
            p |= (uint32_t)(q & 0xFF) << (8 * j);
        }
        packed[cq] = p;
    }
    uint4* dst = (uint4*)(g_qx + (size_t)pix * 32);
    dst[0] = make_uint4(packed[0], packed[1], packed[2], packed[3]);
    dst[1] = make_uint4(packed[4], packed[5], packed[6], packed[7]);
}

// ---------------- kernel 4: int8 3x3 conv via dp4a + fused dequant/bias ------
// Block = 128 threads = 128 consecutive w in one image row; each thread owns
// one output pixel and all 32 output channels (32 int accumulators).
// Weights (9216 B) broadcast from smem.
__global__ void __launch_bounds__(128) k_conv(float* __restrict__ out,
                                              const float* __restrict__ bias) {
    __shared__ uint32_t s_w[OC * 9 * 8]; // [oc][tap][8 words of 4 ic]
    __shared__ float s_b[OC];
    __shared__ float s_scale;
    {
        const uint32_t* gw = (const uint32_t*)g_qw;
        for (int i = threadIdx.x; i < OC * 9 * 8; i += 128) s_w[i] = gw[i];
        if (threadIdx.x < OC) s_b[threadIdx.x] = bias[threadIdx.x];
        if (threadIdx.x == 0) s_scale = g_scale;
    }
    __syncthreads();

    int w = blockIdx.x * 128 + threadIdx.x;
    int h = blockIdx.y;
    int n = blockIdx.z;

    int acc[OC];
    #pragma unroll
    for (int o = 0; o < OC; o++) acc[o] = 0;

    const int8_t* base = g_qx + (size_t)n * HW * 32;

    #pragma unroll 1        // keep body ~4.5KB for I$; oc/word loops fully unrolled
    for (int t = 0; t < 9; t++) {
        int dh = (t >= 6) ? 1 : ((t >= 3) ? 0 : -1);
        int dw = t - (dh + 1) * 3 - 1;
        int hh = h + dh, ww = w + dw;
        uint4 a0, a1;
        if (hh >= 0 && hh < Hh && ww >= 0 && ww < Ww) {
            const uint4* ap = (const uint4*)(base + ((size_t)hh * Ww + ww) * 32);
            a0 = __ldg(ap);
            a1 = __ldg(ap + 1);
        } else {
            a0 = make_uint4(0, 0, 0, 0);
            a1 = a0;
        }
        uint32_t av[8] = {a0.x, a0.y, a0.z, a0.w, a1.x, a1.y, a1.z, a1.w};
        const uint32_t* wt = &s_w[t * 8];
        #pragma unroll
        for (int o = 0; o < OC; o++) {
            const uint32_t* wp = wt + o * 72; // (o*9+t)*8
            int s = acc[o];
            #pragma unroll
            for (int j = 0; j < 8; j++)
                s = __dp4a((int)av[j], (int)wp[j], s);
            acc[o] = s;
        }
    }

    float sc = s_scale;
    float* op = out + (size_t)n * OC * HW + (size_t)h * Ww + w;
    #pragma unroll
    for (int o = 0; o < OC; o++)
        op[(size_t)o * HW] = (float)acc[o] * sc + s_b[o];
}

// ---------------- launch ------------------------------------------------------
extern "C" void kernel_launch(void* const* d_in, const int* in_sizes, int n_in,
                              void* d_out, int out_size) {
    const float* x    = (const float*)d_in[0];
    const float* wgt  = (const float*)d_in[1];
    const float* bias = (const float*)d_in[2];
    float* out        = (float*)d_out;

    k_init<<<1, 1>>>();

    const int n4 = (Nn * Cc * HW) / 4; // 16,777,216 float4
    k_absmax_x<<<2048, 256>>>((const float4*)x, n4);

    k_prep_w<<<1, 256>>>(wgt);

    const long npix = NPIX;
    k_quant_x<<<(int)((npix + 255) / 256), 256>>>(x);

    dim3 grid(Ww / 128, Hh, Nn); // (4, 512, 8)
    k_conv<<<grid, 128>>>(out, bias);
}

// round 6
// speedup vs baseline: 1.1265x; 1.1265x over previous
#include <cuda_runtime.h>
#include <cstdint>

// Problem shape (fixed by the dataset)
#define Nn 8
#define Cc 32
#define Hh 512
#define Ww 512
#define HW (Hh * Ww)          // 262144
#define OC 32
#define NPIX ((long)Nn * HW)  // 2,097,152 pixels

// Padded NHWC int8 activation layout: 514x514 pixels, 32B each, zero halo.
#define PW   514
#define PROW ((size_t)PW * 32)       // bytes per padded row
#define PIMG ((size_t)PW * PW * 32)  // bytes per padded image

// ---------------- device scratch (allocation-free rule: __device__ globals) ---
__device__ unsigned g_amax_x_bits;          // bit pattern of max|x| (nonneg float)
__device__ float    g_scale;                // sx*sw/127^2
__device__ float    g_invsx;                // 127/sx
__device__ int8_t   g_qw[OC * 9 * Cc];      // [oc][tap][ic], tap = kh*3+kw
__device__ int8_t   g_qx[(size_t)Nn * PW * PW * 32]; // padded NHWC int8, ~64.5 MB

// ---------------- kernel -1: zero the 1-pixel halo of g_qx -------------------
// 2052 halo pixels per image (rows 0/513 full + cols 0/513 of rows 1..512).
__global__ void k_zero_halo() {
    int i = blockIdx.x * blockDim.x + threadIdx.x;
    if (i >= Nn * 2052) return;
    int n = i / 2052, j = i % 2052;
    int h, w;
    if (j < 514)        { h = 0;   w = j; }
    else if (j < 1028)  { h = 513; w = j - 514; }
    else { int k = j - 1028; h = (k & 511) + 1; w = (k < 512) ? 0 : 513; }
    uint4* p = (uint4*)(g_qx + (size_t)n * PIMG + (size_t)h * PROW + (size_t)w * 32);
    uint4 z = make_uint4(0, 0, 0, 0);
    p[0] = z; p[1] = z;
}

// ---------------- kernel 0: reset reduction state (graph replays need this) ---
__global__ void k_init() {
    g_amax_x_bits = 0u;
}

// ---------------- kernel 1: max|x| over 67M floats --------------------------
__global__ void k_absmax_x(const float4* __restrict__ x, int n4) {
    float m = 0.f;
    for (int i = blockIdx.x * blockDim.x + threadIdx.x; i < n4;
         i += gridDim.x * blockDim.x) {
        float4 v = x[i];
        m = fmaxf(m, fmaxf(fmaxf(fabsf(v.x), fabsf(v.y)),
                           fmaxf(fabsf(v.z), fabsf(v.w))));
    }
    #pragma unroll
    for (int o = 16; o; o >>= 1) m = fmaxf(m, __shfl_xor_sync(~0u, m, o));
    __shared__ float sm[32];
    int wid = threadIdx.x >> 5;
    if ((threadIdx.x & 31) == 0) sm[wid] = m;
    __syncthreads();
    if (threadIdx.x < 32) {
        float v = (threadIdx.x < (blockDim.x >> 5)) ? sm[threadIdx.x] : 0.f;
        #pragma unroll
        for (int o = 16; o; o >>= 1) v = fmaxf(v, __shfl_xor_sync(~0u, v, o));
        if (threadIdx.x == 0)
            atomicMax(&g_amax_x_bits, __float_as_uint(v)); // nonneg: uint order == float order
    }
}

// ---------------- kernel 2: weight amax + quantize + scales ------------------
__global__ void k_prep_w(const float* __restrict__ w) {
    const int NW = OC * Cc * 9; // 9216
    float m = 0.f;
    for (int i = threadIdx.x; i < NW; i += 256) m = fmaxf(m, fabsf(w[i]));
    #pragma unroll
    for (int o = 16; o; o >>= 1) m = fmaxf(m, __shfl_xor_sync(~0u, m, o));
    __shared__ float sm[8];
    __shared__ float s_sw;
    if ((threadIdx.x & 31) == 0) sm[threadIdx.x >> 5] = m;
    __syncthreads();
    if (threadIdx.x == 0) {
        float v = sm[0];
        #pragma unroll
        for (int j = 1; j < 8; j++) v = fmaxf(v, sm[j]);
        s_sw = v;
    }
    __syncthreads();
    float inv = 127.f / s_sw;
    for (int i = threadIdx.x; i < NW; i += 256) {
        int oc = i / (Cc * 9);
        int r  = i % (Cc * 9);
        int ic = r / 9;
        int t  = r % 9;
        int q = __float2int_rn(w[i] * inv);   // round-half-to-even == jnp.round
        q = max(-127, min(127, q));
        g_qw[(oc * 9 + t) * Cc + ic] = (int8_t)q;
    }
    if (threadIdx.x == 0) {
        float sx = __uint_as_float(g_amax_x_bits);
        g_scale  = sx * s_sw / (127.f * 127.f);
        g_invsx  = 127.f / sx;
    }
}

// ---------------- kernel 3: quantize x, NCHW fp32 -> padded NHWC int8 --------
__global__ void k_quant_x(const float* __restrict__ x) {
    long pix = (long)blockIdx.x * blockDim.x + threadIdx.x;
    if (pix >= NPIX) return;
    int n  = (int)(pix / HW);
    int hw = (int)(pix % HW);
    int h  = hw >> 9;          // /512
    int w  = hw & 511;
    const float* xp = x + (size_t)n * Cc * HW + hw;
    float inv = g_invsx;
    uint32_t packed[8];
    #pragma unroll
    for (int cq = 0; cq < 8; cq++) {
        uint32_t p = 0;
        #pragma unroll
        for (int j = 0; j < 4; j++) {
            float v = __ldg(xp + (size_t)(cq * 4 + j) * HW);
            int q = __float2int_rn(v * inv);
            q = max(-127, min(127, q));
            p |= (uint32_t)(q & 0xFF) << (8 * j);
        }
        packed[cq] = p;
    }
    uint4* dst = (uint4*)(g_qx + (size_t)n * PIMG + (size_t)(h + 1) * PROW
                          + (size_t)(w + 1) * 32);
    dst[0] = make_uint4(packed[0], packed[1], packed[2], packed[3]);
    dst[1] = make_uint4(packed[4], packed[5], packed[6], packed[7]);
}

// ---------------- kernel 4: int8 3x3 conv via mma.sync (IMMA) ----------------
// Implicit GEMM: out[pix, oc] = sum_{tap,ic} A[pix][tap,ic] * W[oc][tap,ic].
// K = 288 = 9 taps x 32 ic; each k=32 MMA chunk is exactly one tap.
// Warp tile: M=16 consecutive w-pixels, N=32 oc (4 x m16n8k32 per tap).
// Block: 8 warps = 128 w; loops over RPB h rows; weights register-resident.

__device__ __forceinline__ void mma_s8(int* c,
                                       uint32_t a0, uint32_t a1, uint32_t a2, uint32_t a3,
                                       uint32_t b0, uint32_t b1) {
    asm volatile(
        "mma.sync.aligned.m16n8k32.row.col.s32.s8.s8.s32 "
        "{%0,%1,%2,%3}, {%4,%5,%6,%7}, {%8,%9}, {%0,%1,%2,%3};\n"
        : "+r"(c[0]), "+r"(c[1]), "+r"(c[2]), "+r"(c[3])
        : "r"(a0), "r"(a1), "r"(a2), "r"(a3), "r"(b0), "r"(b1));
}

#define RPB 8

__global__ void __launch_bounds__(256, 2) k_conv(float* __restrict__ out,
                                                 const float* __restrict__ bias) {
    const int lane = threadIdx.x & 31;
    const int warp = threadIdx.x >> 5;
    const int g    = lane >> 2;   // groupID (pixel within half-tile / oc within n-tile)
    const int tg   = lane & 3;    // thread-in-group (k-word selector)

    const int n  = blockIdx.z;
    const int h0 = blockIdx.y * RPB;
    const int w0 = blockIdx.x * 128 + warp * 16;

    // Weight fragments, register-resident: wf[tap][n-tile][khalf]
    // B (col-major KxN): col oc = nt*8+g, rows ic = tg*4..+3 (b0) / +16 (b1)
    //   == words tg and tg+4 of g_qw[oc][tap][0..31].
    uint32_t wf[9][4][2];
    {
        const uint32_t* qw = (const uint32_t*)g_qw;
        #pragma unroll
        for (int nt = 0; nt < 4; nt++) {
            int oc = nt * 8 + g;
            #pragma unroll
            for (int t = 0; t < 9; t++) {
                const uint32_t* p = qw + (oc * 9 + t) * 8;
                wf[t][nt][0] = __ldg(p + tg);
                wf[t][nt][1] = __ldg(p + tg + 4);
            }
        }
    }
    const float sc = g_scale;
    float bv[8];
    #pragma unroll
    for (int nt = 0; nt < 4; nt++) {
        bv[2 * nt]     = __ldg(bias + nt * 8 + tg * 2);
        bv[2 * nt + 1] = __ldg(bias + nt * 8 + tg * 2 + 1);
    }

    const int8_t* qx = g_qx + (size_t)n * PIMG;

    for (int hi = 0; hi < RPB; hi++) {
        const int h = h0 + hi;
        int acc[4][4];
        #pragma unroll
        for (int nt = 0; nt < 4; nt++) {
            acc[nt][0] = 0; acc[nt][1] = 0; acc[nt][2] = 0; acc[nt][3] = 0;
        }

        #pragma unroll
        for (int t = 0; t < 9; t++) {
            const int dh = t / 3 - 1;
            const int dw = t % 3 - 1;
            // A (row-major MxK): row = pixel g (a0/a2) and g+8 (a1/a3);
            // cols ic tg*4..+3 (lo) / +16 (hi) == words tg / tg+4 of the pixel vec.
            const uint32_t* pix =
                (const uint32_t*)(qx + (size_t)(h + dh + 1) * PROW)
                + (size_t)(w0 + 1 + dw + g) * 8;
            uint32_t a0 = __ldg(pix + tg);
            uint32_t a2 = __ldg(pix + tg + 4);
            uint32_t a1 = __ldg(pix + 64 + tg);       // pixel g+8 (= +8*8 words)
            uint32_t a3 = __ldg(pix + 64 + tg + 4);
            #pragma unroll
            for (int nt = 0; nt < 4; nt++)
                mma_s8(acc[nt], a0, a1, a2, a3, wf[t][nt][0], wf[t][nt][1]);
        }

        // Epilogue: C m16n8 layout -> NCHW fp32.
        // c0/c1: pixel g,   oc nt*8+tg*2 (+1); c2/c3: pixel g+8, same oc.
        float* ob = out + (size_t)n * OC * HW + (size_t)h * Ww + w0;
        #pragma unroll
        for (int nt = 0; nt < 4; nt++) {
            int oc0 = nt * 8 + tg * 2;
            float* p0 = ob + (size_t)oc0 * HW;
            float* p1 = p0 + HW;
            p0[g]     = (float)acc[nt][0] * sc + bv[2 * nt];
            p1[g]     = (float)acc[nt][1] * sc + bv[2 * nt + 1];
            p0[g + 8] = (float)acc[nt][2] * sc + bv[2 * nt];
            p1[g + 8] = (float)acc[nt][3] * sc + bv[2 * nt + 1];
        }
    }
}

// ---------------- launch ------------------------------------------------------
extern "C" void kernel_launch(void* const* d_in, const int* in_sizes, int n_in,
                              void* d_out, int out_size) {
    const float* x    = (const float*)d_in[0];
    const float* wgt  = (const float*)d_in[1];
    const float* bias = (const float*)d_in[2];
    float* out        = (float*)d_out;

    k_zero_halo<<<(Nn * 2052 + 255) / 256, 256>>>();
    k_init<<<1, 1>>>();

    const int n4 = (Nn * Cc * HW) / 4; // 16,777,216 float4
    k_absmax_x<<<2048, 256>>>((const float4*)x, n4);

    k_prep_w<<<1, 256>>>(wgt);

    const long npix = NPIX;
    k_quant_x<<<(int)((npix + 255) / 256), 256>>>(x);

    dim3 grid(Ww / 128, Hh / RPB, Nn); // (4, 64, 8)
    k_conv<<<grid, 256>>>(out, bias);
}

// round 7
// speedup vs baseline: 1.1438x; 1.0153x over previous
#include <cuda_runtime.h>
#include <cstdint>

// Problem shape (fixed by the dataset)
#define Nn 8
#define Cc 32
#define Hh 512
#define Ww 512
#define HW (Hh * Ww)          // 262144
#define OC 32
#define NPIX ((long)Nn * HW)  // 2,097,152 pixels

// Padded NHWC int8 activation layout: 514x514 pixels, 32B each, zero halo.
#define PW   514
#define PROW ((size_t)PW * 32)       // bytes per padded row
#define PIMG ((size_t)PW * PW * 32)  // bytes per padded image

// ---------------- device scratch (allocation-free rule: __device__ globals) ---
__device__ unsigned g_amax_x_bits;          // bit pattern of max|x| (nonneg float)
__device__ float    g_sw;                   // weight absmax
// g_qw word order: slot = (t*8+g)*4+tg, j = 0..7 (half = j>>2, nt = j&3)
//   word[slot*8+j] packs ic = (tg + half*4)*4 .. +3 for oc = nt*8+g, tap t.
__device__ uint32_t g_qw[9 * 8 * 4 * 8];    // 9216 B
__device__ int8_t   g_qx[(size_t)Nn * PW * PW * 32]; // padded NHWC int8, ~64.5 MB

// ---------------- kernel 0: zero halo of g_qx + reset amax -------------------
__global__ void k_zero_halo() {
    if (blockIdx.x == 0 && threadIdx.x == 0) g_amax_x_bits = 0u;
    int i = blockIdx.x * blockDim.x + threadIdx.x;
    if (i >= Nn * 2052) return;
    int n = i / 2052, j = i % 2052;
    int h, w;
    if (j < 514)        { h = 0;   w = j; }
    else if (j < 1028)  { h = 513; w = j - 514; }
    else { int k = j - 1028; h = (k & 511) + 1; w = (k < 512) ? 0 : 513; }
    uint4* p = (uint4*)(g_qx + (size_t)n * PIMG + (size_t)h * PROW + (size_t)w * 32);
    uint4 z = make_uint4(0, 0, 0, 0);
    p[0] = z; p[1] = z;
}

// ---------------- kernel 1: weight absmax + quantize (pre-shuffled layout) ---
// One block of 256 threads; independent of activation scale.
__global__ void k_prep_w(const float* __restrict__ w) {
    const int NW = OC * Cc * 9; // 9216
    float m = 0.f;
    for (int i = threadIdx.x; i < NW; i += 256) m = fmaxf(m, fabsf(w[i]));
    #pragma unroll
    for (int o = 16; o; o >>= 1) m = fmaxf(m, __shfl_xor_sync(~0u, m, o));
    __shared__ float sm[8];
    __shared__ float s_sw;
    if ((threadIdx.x & 31) == 0) sm[threadIdx.x >> 5] = m;
    __syncthreads();
    if (threadIdx.x == 0) {
        float v = sm[0];
        #pragma unroll
        for (int j = 1; j < 8; j++) v = fmaxf(v, sm[j]);
        s_sw = v;
        g_sw = v;
    }
    __syncthreads();
    float inv = 127.f / s_sw;
    for (int i = threadIdx.x; i < 9 * 8 * 4 * 8; i += 256) {
        int slot = i >> 3, j = i & 7;
        int tg = slot & 3, g = (slot >> 2) & 7, t = slot >> 5;
        int nt = j & 3, half = j >> 2;
        int oc  = nt * 8 + g;
        int ic0 = (tg + half * 4) * 4;
        uint32_t p = 0;
        #pragma unroll
        for (int b = 0; b < 4; b++) {
            // OIHW: w[oc][ic][kh][kw], t = kh*3+kw
            int q = __float2int_rn(w[(oc * Cc + ic0 + b) * 9 + t] * inv);
            q = max(-127, min(127, q));
            p |= (uint32_t)(q & 0xFF) << (8 * b);
        }
        g_qw[i] = p;
    }
}

// ---------------- kernel 2: max|x| over 67M floats ---------------------------
__global__ void k_absmax_x(const float4* __restrict__ x, int n4) {
    float m = 0.f;
    for (int i = blockIdx.x * blockDim.x + threadIdx.x; i < n4;
         i += gridDim.x * blockDim.x) {
        float4 v = x[i];
        m = fmaxf(m, fmaxf(fmaxf(fabsf(v.x), fabsf(v.y)),
                           fmaxf(fabsf(v.z), fabsf(v.w))));
    }
    #pragma unroll
    for (int o = 16; o; o >>= 1) m = fmaxf(m, __shfl_xor_sync(~0u, m, o));
    __shared__ float sm[32];
    int wid = threadIdx.x >> 5;
    if ((threadIdx.x & 31) == 0) sm[wid] = m;
    __syncthreads();
    if (threadIdx.x < 32) {
        float v = (threadIdx.x < (blockDim.x >> 5)) ? sm[threadIdx.x] : 0.f;
        #pragma unroll
        for (int o = 16; o; o >>= 1) v = fmaxf(v, __shfl_xor_sync(~0u, v, o));
        if (threadIdx.x == 0)
            atomicMax(&g_amax_x_bits, __float_as_uint(v)); // nonneg: uint order == float order
    }
}

// ---------------- kernel 3: quantize x, NCHW fp32 -> padded NHWC int8 --------
__global__ void k_quant_x(const float* __restrict__ x) {
    long pix = (long)blockIdx.x * blockDim.x + threadIdx.x;
    if (pix >= NPIX) return;
    int n  = (int)(pix / HW);
    int hw = (int)(pix % HW);
    int h  = hw >> 9;          // /512
    int w  = hw & 511;
    const float* xp = x + (size_t)n * Cc * HW + hw;
    float inv = 127.f / __uint_as_float(g_amax_x_bits);
    uint32_t packed[8];
    #pragma unroll
    for (int cq = 0; cq < 8; cq++) {
        uint32_t p = 0;
        #pragma unroll
        for (int j = 0; j < 4; j++) {
            float v = __ldg(xp + (size_t)(cq * 4 + j) * HW);
            int q = __float2int_rn(v * inv);
            q = max(-127, min(127, q));
            p |= (uint32_t)(q & 0xFF) << (8 * j);
        }
        packed[cq] = p;
    }
    uint4* dst = (uint4*)(g_qx + (size_t)n * PIMG + (size_t)(h + 1) * PROW
                          + (size_t)(w + 1) * 32);
    dst[0] = make_uint4(packed[0], packed[1], packed[2], packed[3]);
    dst[1] = make_uint4(packed[4], packed[5], packed[6], packed[7]);
}

// ---------------- kernel 4: int8 3x3 conv via mma.sync (IMMA) ----------------
// Implicit GEMM, K = 288 = 9 taps x 32 ic; each k=32 MMA chunk is one tap.
// Warp tile: M=16 pixels, N=32 oc (4 x m16n8k32 per tap). Weights in smem
// (48B-stride padded slots -> conflict-free LDS.128), ~60 regs, no spills.

__device__ __forceinline__ void mma_s8(int* c,
                                       uint32_t a0, uint32_t a1, uint32_t a2, uint32_t a3,
                                       uint32_t b0, uint32_t b1) {
    asm volatile(
        "mma.sync.aligned.m16n8k32.row.col.s32.s8.s8.s32 "
        "{%0,%1,%2,%3}, {%4,%5,%6,%7}, {%8,%9}, {%0,%1,%2,%3};\n"
        : "+r"(c[0]), "+r"(c[1]), "+r"(c[2]), "+r"(c[3])
        : "r"(a0), "r"(a1), "r"(a2), "r"(a3), "r"(b0), "r"(b1));
}

#define RPB 8

__global__ void __launch_bounds__(256) k_conv(float* __restrict__ out,
                                              const float* __restrict__ bias) {
    // slot stride padded 8 -> 12 words (48 B): LDS.128 bank-conflict-free.
    __shared__ uint32_t s_w[9 * 8 * 4 * 12]; // 13824 B
    __shared__ float s_scale;
    for (int i = threadIdx.x; i < 9 * 8 * 4 * 8; i += 256)
        s_w[(i >> 3) * 12 + (i & 7)] = g_qw[i];
    if (threadIdx.x == 0)
        s_scale = __uint_as_float(g_amax_x_bits) * g_sw * (1.f / 16129.f);
    __syncthreads();

    const int lane = threadIdx.x & 31;
    const int warp = threadIdx.x >> 5;
    const int g    = lane >> 2;   // pixel within half-tile / oc within n-tile
    const int tg   = lane & 3;    // k-word selector

    const int n  = blockIdx.z;
    const int h0 = blockIdx.y * RPB;
    const int w0 = blockIdx.x * 128 + warp * 16;

    const float sc = s_scale;
    float bv[8];
    #pragma unroll
    for (int nt = 0; nt < 4; nt++) {
        bv[2 * nt]     = __ldg(bias + nt * 8 + tg * 2);
        bv[2 * nt + 1] = __ldg(bias + nt * 8 + tg * 2 + 1);
    }

    const int8_t* qx = g_qx + (size_t)n * PIMG;
    const uint32_t* wslot = &s_w[(g * 4 + tg) * 12]; // tap t adds t*8*4*12

    for (int hi = 0; hi < RPB; hi++) {
        const int h = h0 + hi;
        int acc[4][4];
        #pragma unroll
        for (int nt = 0; nt < 4; nt++) {
            acc[nt][0] = 0; acc[nt][1] = 0; acc[nt][2] = 0; acc[nt][3] = 0;
        }

        #pragma unroll
        for (int t = 0; t < 9; t++) {
            const int dh = t / 3 - 1;
            const int dw = t % 3 - 1;
            const uint32_t* pix =
                (const uint32_t*)(qx + (size_t)(h + dh + 1) * PROW)
                + (size_t)(w0 + 1 + dw + g) * 8;
            uint32_t a0 = __ldg(pix + tg);
            uint32_t a2 = __ldg(pix + tg + 4);
            uint32_t a1 = __ldg(pix + 64 + tg);       // pixel g+8
            uint32_t a3 = __ldg(pix + 64 + tg + 4);

            const uint4* bp = (const uint4*)(wslot + t * (8 * 4 * 12));
            uint4 b0 = bp[0];  // nt = 0..3, k-half 0
            uint4 b1 = bp[1];  // nt = 0..3, k-half 1
            mma_s8(acc[0], a0, a1, a2, a3, b0.x, b1.x);
            mma_s8(acc[1], a0, a1, a2, a3, b0.y, b1.y);
            mma_s8(acc[2], a0, a1, a2, a3, b0.z, b1.z);
            mma_s8(acc[3], a0, a1, a2, a3, b0.w, b1.w);
        }

        // Epilogue: C m16n8 -> NCHW fp32.
        float* ob = out + (size_t)n * OC * HW + (size_t)h * Ww + w0;
        #pragma unroll
        for (int nt = 0; nt < 4; nt++) {
            int oc0 = nt * 8 + tg * 2;
            float* p0 = ob + (size_t)oc0 * HW;
            float* p1 = p0 + HW;
            p0[g]     = (float)acc[nt][0] * sc + bv[2 * nt];
            p1[g]     = (float)acc[nt][1] * sc + bv[2 * nt + 1];
            p0[g + 8] = (float)acc[nt][2] * sc + bv[2 * nt];
            p1[g + 8] = (float)acc[nt][3] * sc + bv[2 * nt + 1];
        }
    }
}

// ---------------- launch ------------------------------------------------------
extern "C" void kernel_launch(void* const* d_in, const int* in_sizes, int n_in,
                              void* d_out, int out_size) {
    const float* x    = (const float*)d_in[0];
    const float* wgt  = (const float*)d_in[1];
    const float* bias = (const float*)d_in[2];
    float* out        = (float*)d_out;

    k_zero_halo<<<(Nn * 2052 + 255) / 256, 256>>>();
    k_prep_w<<<1, 256>>>(wgt);

    const int n4 = (Nn * Cc * HW) / 4; // 16,777,216 float4
    k_absmax_x<<<2048, 256>>>((const float4*)x, n4);

    const long npix = NPIX;
    k_quant_x<<<(int)((npix + 255) / 256), 256>>>(x);

    dim3 grid(Ww / 128, Hh / RPB, Nn); // (4, 64, 8)
    k_conv<<<grid, 256>>>(out, bias);
}

// round 9
// speedup vs baseline: 1.2789x; 1.1181x over previous
#include <cuda_runtime.h>
#include <cstdint>

// Problem shape (fixed by the dataset)
#define Nn 8
#define Cc 32
#define Hh 512
#define Ww 512
#define HW (Hh * Ww)          // 262144
#define OC 32

// ---------------- device scratch (allocation-free rule) ----------------------
__device__ float    g_blockmax[2048];   // per-block |x| maxima (no atomics, no init)
__device__ float    g_sw;               // weight absmax
// g_qw word order (R7-proven): i -> slot=i>>3 (slot=(t*8+g)*4+tg), j=i&7
//   (half=j>>2, nt=j&3); word packs ic=(tg+half*4)*4..+3 for oc=nt*8+g, tap t.
__device__ uint32_t g_qw[9 * 8 * 4 * 8]; // 9216 B

// ---------------- kernel 1: x per-block absmax (+ weight prep in block 0) ----
__global__ void k_absmax(const float4* __restrict__ x, const float* __restrict__ w,
                         int n4) {
    __shared__ float sred[8];
    float m = 0.f;
    for (int i = blockIdx.x * blockDim.x + threadIdx.x; i < n4;
         i += gridDim.x * blockDim.x) {
        float4 v = x[i];
        m = fmaxf(m, fmaxf(fmaxf(fabsf(v.x), fabsf(v.y)),
                           fmaxf(fabsf(v.z), fabsf(v.w))));
    }
    #pragma unroll
    for (int o = 16; o; o >>= 1) m = fmaxf(m, __shfl_xor_sync(~0u, m, o));
    if ((threadIdx.x & 31) == 0) sred[threadIdx.x >> 5] = m;
    __syncthreads();
    if (threadIdx.x == 0) {
        float v = sred[0];
        #pragma unroll
        for (int j = 1; j < 8; j++) v = fmaxf(v, sred[j]);
        g_blockmax[blockIdx.x] = v;
    }

    if (blockIdx.x == 0) {   // weight absmax + quantize + pre-shuffle
        __syncthreads();
        float mw = 0.f;
        for (int i = threadIdx.x; i < 9216; i += 256) mw = fmaxf(mw, fabsf(w[i]));
        #pragma unroll
        for (int o = 16; o; o >>= 1) mw = fmaxf(mw, __shfl_xor_sync(~0u, mw, o));
        if ((threadIdx.x & 31) == 0) sred[threadIdx.x >> 5] = mw;
        __syncthreads();
        __shared__ float s_sw;
        if (threadIdx.x == 0) {
            float v = sred[0];
            #pragma unroll
            for (int j = 1; j < 8; j++) v = fmaxf(v, sred[j]);
            s_sw = v;
            g_sw = v;
        }
        __syncthreads();
        float inv = 127.f / s_sw;
        for (int i = threadIdx.x; i < 9 * 8 * 4 * 8; i += 256) {
            int slot = i >> 3, j = i & 7;
            int tg = slot & 3, g = (slot >> 2) & 7, t = slot >> 5;
            int nt = j & 3, half = j >> 2;
            int oc  = nt * 8 + g;
            int ic0 = (tg + half * 4) * 4;
            uint32_t p = 0;
            #pragma unroll
            for (int b = 0; b < 4; b++) {
                int q = __float2int_rn(w[(oc * Cc + ic0 + b) * 9 + t] * inv);
                q = max(-127, min(127, q));
                p |= (uint32_t)(q & 0xFF) << (8 * b);
            }
            g_qw[i] = p;
        }
    }
}

// ---------------- kernel 2: fused quantize + int8 3x3 conv (IMMA) ------------
// CTA: 128-wide strip x ROWS output rows. fp32 NCHW rows are streamed,
// quantized in-register, staged as int8 NHWC pixels (32 B) in an 8-deep
// smem ring (132-px rows incl. halo cols). MMA layout identical to R7.

__device__ __forceinline__ void mma_s8(int* c,
                                       uint32_t a0, uint32_t a1, uint32_t a2, uint32_t a3,
                                       uint32_t b0, uint32_t b1) {
    asm volatile(
        "mma.sync.aligned.m16n8k32.row.col.s32.s8.s8.s32 "
        "{%0,%1,%2,%3}, {%4,%5,%6,%7}, {%8,%9}, {%0,%1,%2,%3};\n"
        : "+r"(c[0]), "+r"(c[1]), "+r"(c[2]), "+r"(c[3])
        : "r"(a0), "r"(a1), "r"(a2), "r"(a3), "r"(b0), "r"(b1));
}

#define ROWS 16
#define RSTRIDE 4224   // 132 px * 32 B

// Full (load+quant+store) row fill: used for the 3-row prologue.
// Ring buf holds input row r: px 1..128 = w0..w0+127; px 0 / 129 = halo cols.
__device__ __forceinline__ void load_row_full(char* dst, const float* __restrict__ xn,
                                              int r, int w0, float inv) {
    const int tid = threadIdx.x;
    const int pxm = (tid & 127) + 1, hf = tid >> 7;
    const bool vr = ((unsigned)r < (unsigned)Hh);
    const float* p = xn + (size_t)(hf * 16) * HW + (size_t)(vr ? r : 0) * Ww
                   + (w0 + (tid & 127));
    uint32_t wd[4];
    #pragma unroll
    for (int q4 = 0; q4 < 4; q4++) {
        uint32_t pw = 0;
        #pragma unroll
        for (int b = 0; b < 4; b++) {
            float v = vr ? __ldg(p + (size_t)(q4 * 4 + b) * HW) : 0.f;
            int q = max(-127, min(127, __float2int_rn(v * inv)));
            pw |= (uint32_t)(q & 0xFF) << (8 * b);
        }
        wd[q4] = pw;
    }
    *(uint4*)(dst + pxm * 32 + hf * 16) = make_uint4(wd[0], wd[1], wd[2], wd[3]);
    if (tid < 64) {   // 2 halo columns x 32 ch
        int hp = (tid < 32) ? 0 : 129;
        int wh = w0 - 1 + hp;
        int ch = tid & 31;
        float v = 0.f;
        if (vr && wh >= 0 && wh < Ww)
            v = __ldg(xn + (size_t)ch * HW + (size_t)r * Ww + wh);
        int q = max(-127, min(127, __float2int_rn(v * inv)));
        *(int8_t*)(dst + hp * 32 + ch) = (int8_t)q;
    }
}

__global__ void __launch_bounds__(256) k_conv(const float* __restrict__ x,
                                              float* __restrict__ out,
                                              const float* __restrict__ bias) {
    __shared__ uint32_t s_w[9 * 8 * 4 * 12];  // 13824 B, 48B slot stride
    __shared__ char     s_a[8 * RSTRIDE];     // 33792 B ring
    __shared__ float    s_red[8];
    __shared__ float    s_scale, s_inv;

    const int tid  = threadIdx.x;
    const int warp = tid >> 5, lane = tid & 31;
    const int g    = lane >> 2, tg = lane & 3;
    const int n  = blockIdx.z;
    const int h0 = blockIdx.y * ROWS;
    const int w0 = blockIdx.x * 128;
    const float* xn = x + (size_t)n * Cc * HW;

    // final absmax from per-block maxima
    {
        float m = 0.f;
        for (int j = tid; j < 2048; j += 256) m = fmaxf(m, g_blockmax[j]);
        #pragma unroll
        for (int o = 16; o; o >>= 1) m = fmaxf(m, __shfl_xor_sync(~0u, m, o));
        if (lane == 0) s_red[warp] = m;
    }
    __syncthreads();
    if (tid == 0) {
        float v = s_red[0];
        #pragma unroll
        for (int j = 1; j < 8; j++) v = fmaxf(v, s_red[j]);
        s_scale = v * g_sw * (1.f / 16129.f);
        s_inv   = 127.f / v;
    }
    __syncthreads();
    const float inv = s_inv, sc = s_scale;

    // weights -> smem; prologue rows h0-1, h0, h0+1 -> bufs 0,1,2
    for (int i = tid; i < 9 * 8 * 4 * 8; i += 256)
        s_w[(i >> 3) * 12 + (i & 7)] = g_qw[i];
    load_row_full(s_a + 0 * RSTRIDE, xn, h0 - 1, w0, inv);
    load_row_full(s_a + 1 * RSTRIDE, xn, h0,     w0, inv);
    load_row_full(s_a + 2 * RSTRIDE, xn, h0 + 1, w0, inv);
    __syncthreads();

    float bv[8];
    #pragma unroll
    for (int nt = 0; nt < 4; nt++) {
        bv[2 * nt]     = __ldg(bias + nt * 8 + tg * 2);
        bv[2 * nt + 1] = __ldg(bias + nt * 8 + tg * 2 + 1);
    }

    const int pxm = (tid & 127) + 1, hf = tid >> 7;
    const float* pmain = xn + (size_t)(hf * 16) * HW + (w0 + (tid & 127));
    const int hp = (tid < 32) ? 0 : 129;
    const int wh = w0 - 1 + hp;
    const bool whv = (wh >= 0) && (wh < Ww);
    const uint32_t* wslot = &s_w[(g * 4 + tg) * 12];

    #pragma unroll 1
    for (int i = 0; i < ROWS; i++) {
        // ---- phase A: issue fp32 loads for input row h0+i+2 ----------------
        float f[16];
        float fhalo = 0.f;
        const int rp = h0 + i + 2;
        const bool pf = (i <= ROWS - 2);
        const bool vr = pf && (rp < Hh);
        #pragma unroll
        for (int k = 0; k < 16; k++)
            f[k] = vr ? __ldg(pmain + (size_t)rp * Ww + (size_t)k * HW) : 0.f;
        if (tid < 64 && vr && whv)
            fhalo = __ldg(xn + (size_t)(tid & 31) * HW + (size_t)rp * Ww + wh);

        // ---- phase B: MMA for output row h0+i (bufs i, i+1, i+2) -----------
        int acc[4][4];
        #pragma unroll
        for (int nt = 0; nt < 4; nt++) {
            acc[nt][0] = 0; acc[nt][1] = 0; acc[nt][2] = 0; acc[nt][3] = 0;
        }
        #pragma unroll
        for (int t = 0; t < 9; t++) {
            const int dh = t / 3, dw = t % 3;
            const char* ap = s_a + ((i + dh) & 7) * RSTRIDE
                           + (warp * 16 + g + dw) * 32 + tg * 4;
            uint32_t a0 = *(const uint32_t*)ap;
            uint32_t a2 = *(const uint32_t*)(ap + 16);
            uint32_t a1 = *(const uint32_t*)(ap + 256);   // pixel g+8
            uint32_t a3 = *(const uint32_t*)(ap + 272);
            const uint4* bp = (const uint4*)(wslot + t * (8 * 4 * 12));
            uint4 b0 = bp[0];
            uint4 b1 = bp[1];
            mma_s8(acc[0], a0, a1, a2, a3, b0.x, b1.x);
            mma_s8(acc[1], a0, a1, a2, a3, b0.y, b1.y);
            mma_s8(acc[2], a0, a1, a2, a3, b0.z, b1.z);
            mma_s8(acc[3], a0, a1, a2, a3, b0.w, b1.w);
        }
        // epilogue: C m16n8 -> NCHW fp32
        {
            const int h = h0 + i;
            float* ob = out + (size_t)n * OC * HW + (size_t)h * Ww
                      + (w0 + warp * 16);
            #pragma unroll
            for (int nt = 0; nt < 4; nt++) {
                int oc0 = nt * 8 + tg * 2;
                float* p0 = ob + (size_t)oc0 * HW;
                float* p1 = p0 + HW;
                p0[g]     = (float)acc[nt][0] * sc + bv[2 * nt];
                p1[g]     = (float)acc[nt][1] * sc + bv[2 * nt + 1];
                p0[g + 8] = (float)acc[nt][2] * sc + bv[2 * nt];
                p1[g + 8] = (float)acc[nt][3] * sc + bv[2 * nt + 1];
            }
        }

        // ---- phase D: quantize + store row rp into buf (i+3)&7 -------------
        if (pf) {
            char* dst = s_a + ((i + 3) & 7) * RSTRIDE;
            uint32_t wd[4];
            #pragma unroll
            for (int q4 = 0; q4 < 4; q4++) {
                uint32_t pw = 0;
                #pragma unroll
                for (int b = 0; b < 4; b++) {
                    int q = max(-127, min(127, __float2int_rn(f[q4 * 4 + b] * inv)));
                    pw |= (uint32_t)(q & 0xFF) << (8 * b);
                }
                wd[q4] = pw;
            }
            *(uint4*)(dst + pxm * 32 + hf * 16) =
                make_uint4(wd[0], wd[1], wd[2], wd[3]);
            if (tid < 64) {
                int q = max(-127, min(127, __float2int_rn(fhalo * inv)));
                *(int8_t*)(dst + hp * 32 + (tid & 31)) = (int8_t)q;
            }
        }
        __syncthreads();
    }
}

// ---------------- launch ------------------------------------------------------
extern "C" void kernel_launch(void* const* d_in, const int* in_sizes, int n_in,
                              void* d_out, int out_size) {
    const float* x    = (const float*)d_in[0];
    const float* wgt  = (const float*)d_in[1];
    const float* bias = (const float*)d_in[2];
    float* out        = (float*)d_out;

    const int n4 = (Nn * Cc * HW) / 4; // 16,777,216 float4
    k_absmax<<<2048, 256>>>((const float4*)x, wgt, n4);

    dim3 grid(Ww / 128, Hh / ROWS, Nn); // (4, 32, 8)
    k_conv<<<grid, 256>>>(x, out, bias);
}